// round 1
// baseline (speedup 1.0000x reference)
#include <cuda_runtime.h>
#include <cuda_bf16.h>
#include <cstdint>

#define BATCH 256
#define SEQ   512
#define HID   512
#define VOCAB 128

#define CLUSTER_SZ 8
#define NUM_CLUSTERS 16          // 16*8 = 128 CTAs
#define ROWS_PER_CL 16           // 16*16 = 256 batch rows
#define WCOLS 64                 // HID / CLUSTER_SZ
#define VCOLS 16                 // VOCAB / CLUSTER_SZ
#define NTHREADS 256

// SMEM layout (floats)
#define WHH_F   (512*64)         // 32768
#define WHO_F   (512*16)         // 8192
#define HT_F    (512*16)         // 8192
#define SCR_F   4096
#define OFF_WHO (WHH_F)                  // 32768
#define OFF_HT  (OFF_WHO + WHO_F)        // 40960
#define OFF_SCR (OFF_HT + HT_F)          // 49152
#define OFF_BO  (OFF_SCR + SCR_F)        // 53248
#define OFF_TOK (OFF_BO + 16)            // 53264 (ints)
#define SMEM_BYTES ((OFF_TOK + 16) * 4 + 64)

// scratch for E2 = embedding @ W_ih + b_ih + b_hh  : [VOCAB][HID]
__device__ float d_E2[VOCAB * HID];

__device__ __forceinline__ uint32_t smem_u32(const void* p) {
    uint32_t a;
    asm("{ .reg .u64 t; cvta.to.shared.u64 t, %1; cvt.u32.u64 %0, t; }"
        : "=r"(a) : "l"(p));
    return a;
}

__device__ __forceinline__ void st_cluster_f32(uint32_t addr, int rank, float v) {
    uint32_t rem;
    asm volatile("mapa.shared::cluster.u32 %0, %1, %2;"
                 : "=r"(rem) : "r"(addr), "r"(rank));
    asm volatile("st.shared::cluster.f32 [%0], %1;"
                 :: "r"(rem), "f"(v) : "memory");
}

__device__ __forceinline__ void cluster_sync_() {
    asm volatile("barrier.cluster.arrive.aligned;" ::: "memory");
    asm volatile("barrier.cluster.wait.aligned;" ::: "memory");
}

// 16-FMA expansion: acc[r*4+c] += h4[r] * w4[c]
#define FMA16(ACC, H4, W4) do {                                   \
    ACC[0]  += (H4).x * (W4).x;  ACC[1]  += (H4).x * (W4).y;      \
    ACC[2]  += (H4).x * (W4).z;  ACC[3]  += (H4).x * (W4).w;      \
    ACC[4]  += (H4).y * (W4).x;  ACC[5]  += (H4).y * (W4).y;      \
    ACC[6]  += (H4).y * (W4).z;  ACC[7]  += (H4).y * (W4).w;      \
    ACC[8]  += (H4).z * (W4).x;  ACC[9]  += (H4).z * (W4).y;      \
    ACC[10] += (H4).z * (W4).z;  ACC[11] += (H4).z * (W4).w;      \
    ACC[12] += (H4).w * (W4).x;  ACC[13] += (H4).w * (W4).y;      \
    ACC[14] += (H4).w * (W4).z;  ACC[15] += (H4).w * (W4).w;      \
} while (0)

// ---------------------------------------------------------------------------
// E2[v][i] = sum_k embedding[v][k] * W_ih[k][i] + b_ih[i] + b_hh[i]
// ---------------------------------------------------------------------------
__global__ void e2_kernel(const float* __restrict__ emb,
                          const float* __restrict__ Wih,
                          const float* __restrict__ bih,
                          const float* __restrict__ bhh) {
    __shared__ float er[HID];
    int v = blockIdx.x;
    int i = threadIdx.x;
    er[i] = emb[v * HID + i];
    __syncthreads();
    float acc = 0.f;
#pragma unroll 8
    for (int k = 0; k < HID; k++)
        acc += er[k] * Wih[k * HID + i];
    d_E2[v * HID + i] = acc + bih[i] + bhh[i];
}

// ---------------------------------------------------------------------------
// Persistent cluster RNN kernel.
// Cluster of 8 CTAs handles 16 batch rows through all 512 steps.
// CTA rank r owns W_hh cols [r*64, r*64+64) and W_ho cols [r*16, r*16+16).
// hT SMEM buffer [512][16] ([j][row]) holds the full current h for the
// cluster's 16 rows, all-gathered via DSMEM each step.
// ---------------------------------------------------------------------------
extern __shared__ float sm[];

__global__ void __launch_bounds__(NTHREADS, 1) __cluster_dims__(CLUSTER_SZ, 1, 1)
rnn_kernel(const int* __restrict__ x,
           const float* __restrict__ Whh_g,
           const float* __restrict__ Who_g,
           const float* __restrict__ bo_g,
           float* __restrict__ out,
           int write_h) {
    float* whh  = sm;                 // [512][64]
    float* who  = sm + OFF_WHO;       // [512][16]
    float* ht   = sm + OFF_HT;        // [512][16]  ([j][row])
    float* scr  = sm + OFF_SCR;       // [4096]
    float* bo_s = sm + OFF_BO;        // [16]
    int*   toks = (int*)(sm + OFF_TOK); // [16]

    const int tid     = threadIdx.x;
    const int bx      = blockIdx.x;
    const int rank    = bx & (CLUSTER_SZ - 1);
    const int rowBase = (bx >> 3) * ROWS_PER_CL;
    const int cbase   = rank * WCOLS;
    const int vbase   = rank * VCOLS;

    // ---- load weight slices into SMEM ----
    for (int i = tid; i < WHH_F / 4; i += NTHREADS) {          // 8192 float4
        int j = i >> 4, c4 = i & 15;
        ((float4*)whh)[i] = *(const float4*)(Whh_g + j * HID + cbase + c4 * 4);
    }
    for (int i = tid; i < WHO_F / 4; i += NTHREADS) {          // 2048 float4
        int j = i >> 2, v4 = i & 3;
        ((float4*)who)[i] = *(const float4*)(Who_g + j * VOCAB + vbase + v4 * 4);
    }
    for (int i = tid; i < HT_F; i += NTHREADS) ht[i] = 0.f;    // h0 = 0
    if (tid < 16) bo_s[tid] = bo_g[vbase + tid];
    __syncthreads();

    // thread mapping GEMM1: 4 j-groups x 4 row-groups x 16 col-groups
    const int jg  = tid >> 6;
    const int rg  = (tid >> 4) & 3;
    const int cg  = tid & 15;
    // thread mapping GEMM2: 16 j-groups x 4 row-groups x 4 v-groups
    const int jg2 = tid >> 4;
    const int rg2 = (tid >> 2) & 3;
    const int vg2 = tid & 3;

    const uint32_t ht_u32 = smem_u32(ht);

    for (int t = 0; t < SEQ; t++) {
        // ---- tokens for this step ----
        if (tid < ROWS_PER_CL)
            toks[tid] = x[(rowBase + tid) * SEQ + t];
        __syncthreads();   // toks ready; also fences scratch reuse from prev iter

        // ---- prefetch E2 rows (L2-resident) for the 4 outputs this thread
        //      finalizes: o = tid + k*256 -> (r = o>>6, c = o&63) ----
        float e2v[4];
#pragma unroll
        for (int k = 0; k < 4; k++) {
            int o = tid + (k << 8);
            int r = o >> 6, c = o & 63;
            e2v[k] = __ldg(&d_E2[toks[r] * HID + cbase + c]);
        }

        // ---- GEMM1: acc[16 rows x 64 cols] partials over own j-range ----
        float acc[16];
#pragma unroll
        for (int i = 0; i < 16; i++) acc[i] = 0.f;
        {
            const int j0 = jg << 7;
#pragma unroll 4
            for (int j = j0; j < j0 + 128; j++) {
                float4 h4 = ((const float4*)ht)[(j << 2) + rg];
                float4 w4 = ((const float4*)whh)[(j << 4) + cg];
                FMA16(acc, h4, w4);
            }
        }
#pragma unroll
        for (int rr = 0; rr < 4; rr++)
#pragma unroll
            for (int cc = 0; cc < 4; cc++)
                scr[(jg << 10) + ((rg * 4 + rr) << 6) + cg * 4 + cc] = acc[rr * 4 + cc];
        __syncthreads();

        // ---- finalize h_new (reduce 4 partials + E2 + tanh) ----
        float hn[4];
#pragma unroll
        for (int k = 0; k < 4; k++) {
            int o = tid + (k << 8);
            float v = e2v[k] + scr[o] + scr[o + 1024] + scr[o + 2048] + scr[o + 3072];
            hn[k] = tanhf(v);
        }

        // all CTAs done reading hT (this GEMM1 + previous GEMM2)
        cluster_sync_();

        // ---- all-gather h_new slice into every cluster CTA's hT ----
#pragma unroll
        for (int k = 0; k < 4; k++) {
            int o = tid + (k << 8);
            int r = o >> 6, c = o & 63;
            uint32_t a = ht_u32 + (uint32_t)(((cbase + c) << 4) + r) * 4u;
#pragma unroll
            for (int p = 0; p < CLUSTER_SZ; p++)
                st_cluster_f32(a, p, hn[k]);
        }

        cluster_sync_();   // hT now holds h_{t+1} everywhere

        // ---- GEMM2: y_t[16 rows x 16 vocab] = h_{t+1} @ W_ho slice ----
        float acc2[16];
#pragma unroll
        for (int i = 0; i < 16; i++) acc2[i] = 0.f;
        {
            const int j0 = jg2 << 5;
#pragma unroll 4
            for (int j = j0; j < j0 + 32; j++) {
                float4 h4 = ((const float4*)ht)[(j << 2) + rg2];
                float4 w4 = ((const float4*)who)[(j << 2) + vg2];
                FMA16(acc2, h4, w4);
            }
        }
#pragma unroll
        for (int rr = 0; rr < 4; rr++)
#pragma unroll
            for (int vv = 0; vv < 4; vv++)
                scr[(jg2 << 8) + ((rg2 * 4 + rr) << 4) + vg2 * 4 + vv] = acc2[rr * 4 + vv];
        __syncthreads();

        {
            int r = tid >> 4, v = tid & 15;
            float y = bo_s[v];
#pragma unroll
            for (int g = 0; g < 16; g++) y += scr[(g << 8) + tid];
            out[((long long)(rowBase + r) * SEQ + t) * VOCAB + vbase + v] = y;
        }
        // scratch-reuse hazard vs next iteration handled by the toks
        // __syncthreads at the top of the loop.
    }

    // ---- final hidden state (second output) ----
    if (write_h) {
        float* hout = out + (long long)BATCH * SEQ * VOCAB;
#pragma unroll
        for (int k = 0; k < 4; k++) {
            int o = tid + (k << 8);
            int r = o >> 6, c = o & 63;
            hout[(rowBase + r) * HID + cbase + c] = ht[((cbase + c) << 4) + r];
        }
    }
}

// ---------------------------------------------------------------------------
extern "C" void kernel_launch(void* const* d_in, const int* in_sizes, int n_in,
                              void* d_out, int out_size) {
    const int*   x    = (const int*)  d_in[0];
    const float* emb  = (const float*)d_in[1];
    const float* Wih  = (const float*)d_in[2];
    const float* bih  = (const float*)d_in[3];
    const float* Whh  = (const float*)d_in[4];
    const float* bhh  = (const float*)d_in[5];
    const float* Who  = (const float*)d_in[6];
    const float* bo   = (const float*)d_in[7];
    float* out = (float*)d_out;

    int write_h = (out_size >= BATCH * SEQ * VOCAB + BATCH * HID) ? 1 : 0;

    cudaFuncSetAttribute(rnn_kernel,
                         cudaFuncAttributeMaxDynamicSharedMemorySize, SMEM_BYTES);

    e2_kernel<<<VOCAB, HID>>>(emb, Wih, bih, bhh);
    rnn_kernel<<<NUM_CLUSTERS * CLUSTER_SZ, NTHREADS, SMEM_BYTES>>>(
        x, Whh, Who, bo, out, write_h);
}

// round 2
// speedup vs baseline: 2.6368x; 2.6368x over previous
#include <cuda_runtime.h>
#include <cstdint>

#define BATCH 256
#define SEQ   512
#define HID   512
#define VOCAB 128

#define CLUSTER_SZ   8
#define NUM_CLUSTERS 16          // 128 CTAs total, 1 wave
#define ROWS_PER_CL  16
#define WCOLS        64          // HID / CLUSTER_SZ
#define NTHREADS     256

// ---------------- SMEM layout (floats) for rnn kernel ----------------
#define WHH_F      (512*64)              // 32768 (128KB)
#define HT_F       (512*16)              // 8192  (32KB) per buffer, layout [j][16 rows]
#define SCR_STRIDE 68                    // padded row stride (floats) -> fewer bank conflicts
#define SCR_JG     (16*SCR_STRIDE)       // 1088 per jg block
#define SCR_F      (4*SCR_JG)            // 4352
#define OFF_HT0    (WHH_F)
#define OFF_HT1    (OFF_HT0 + HT_F)
#define OFF_SCR    (OFF_HT1 + HT_F)
#define OFF_TOK    (OFF_SCR + SCR_F)
#define SMEM_F     (OFF_TOK + 16)
#define SMEM_BYTES (SMEM_F * 4)          // ~214KB < 227KB max

// device scratch (allocation-free rule: __device__ globals)
__device__ float d_E2[VOCAB * HID];                       // embedding@W_ih + b_ih + b_hh
__device__ float d_H[(size_t)BATCH * SEQ * HID];          // all hidden states (256MB)

typedef unsigned long long ull;

__device__ __forceinline__ uint32_t smem_u32(const void* p) {
    uint32_t a;
    asm("{ .reg .u64 t; cvta.to.shared.u64 t, %1; cvt.u32.u64 %0, t; }"
        : "=r"(a) : "l"(p));
    return a;
}

// packed fp32x2 FMA: acc.{lo,hi} += a.{lo,hi} * b.{lo,hi}
#define FFMA2(ACC, A, B) \
    asm("fma.rn.f32x2 %0, %1, %2, %0;" : "+l"(ACC) : "l"(A), "l"(B))

__device__ __forceinline__ ull dup2(float v) {
    ull r; unsigned u = __float_as_uint(v);
    asm("mov.b64 %0, {%1, %1};" : "=l"(r) : "r"(u));
    return r;
}
__device__ __forceinline__ float2 unpk(ull v) {
    unsigned lo, hi;
    asm("mov.b64 {%0, %1}, %2;" : "=r"(lo), "=r"(hi) : "l"(v));
    float2 f; f.x = __uint_as_float(lo); f.y = __uint_as_float(hi);
    return f;
}

__device__ __forceinline__ void st_cluster_v4(uint32_t addr, int rank,
                                              float a, float b, float c, float d) {
    uint32_t rem;
    asm volatile("mapa.shared::cluster.u32 %0, %1, %2;"
                 : "=r"(rem) : "r"(addr), "r"(rank));
    asm volatile("st.shared::cluster.v4.f32 [%0], {%1,%2,%3,%4};"
                 :: "r"(rem), "f"(a), "f"(b), "f"(c), "f"(d) : "memory");
}

__device__ __forceinline__ void cluster_sync_() {
    asm volatile("barrier.cluster.arrive.aligned;" ::: "memory");
    asm volatile("barrier.cluster.wait.aligned;" ::: "memory");
}

// ---------------------------------------------------------------------------
// E2[v][i] = sum_k embedding[v][k] * W_ih[k][i] + b_ih[i] + b_hh[i]
// ---------------------------------------------------------------------------
__global__ void e2_kernel(const float* __restrict__ emb,
                          const float* __restrict__ Wih,
                          const float* __restrict__ bih,
                          const float* __restrict__ bhh) {
    __shared__ float er[HID];
    int v = blockIdx.x, i = threadIdx.x;
    er[i] = emb[v * HID + i];
    __syncthreads();
    float acc = 0.f;
#pragma unroll 8
    for (int k = 0; k < HID; k++) acc += er[k] * Wih[k * HID + i];
    d_E2[v * HID + i] = acc + bih[i] + bhh[i];
}

// ---------------------------------------------------------------------------
// Persistent cluster RNN. Cluster of 8 CTAs x 16 batch rows.
// CTA rank r owns W_hh cols [r*64, (r+1)*64). Sequential loop computes only
// h_{t+1}; y is deferred (h stored to d_H). One cluster barrier per step.
// ---------------------------------------------------------------------------
extern __shared__ float sm[];

__global__ void __launch_bounds__(NTHREADS, 1) __cluster_dims__(CLUSTER_SZ, 1, 1)
rnn_kernel(const int* __restrict__ x,
           const float* __restrict__ Whh_g,
           float* __restrict__ out,
           int write_h) {
    float* whh = sm;                       // [512 j][64 c]
    float* ht0 = sm + OFF_HT0;             // [512 j][16 rows]
    float* ht1 = sm + OFF_HT1;
    float* scr = sm + OFF_SCR;             // [4 jg][16 rows x stride 68]
    int*  toks = (int*)(sm + OFF_TOK);     // [16]

    const int tid     = threadIdx.x;
    const int bx      = blockIdx.x;
    const int rank    = bx & (CLUSTER_SZ - 1);
    const int rowBase = (bx >> 3) * ROWS_PER_CL;
    const int cbase   = rank * WCOLS;

    // ---- load W_hh slice, init h0 buffer ----
    for (int i = tid; i < WHH_F / 4; i += NTHREADS) {          // 8192 float4
        int j = i >> 4, c4 = i & 15;
        ((float4*)whh)[i] = *(const float4*)(Whh_g + j * HID + cbase + c4 * 4);
    }
    for (int i = tid; i < HT_F / 4; i += NTHREADS)
        ((float4*)ht0)[i] = make_float4(0.f, 0.f, 0.f, 0.f);
    __syncthreads();

    // GEMM mapping: jg (K-split 4) x rg (4 row-groups) x cg (16 col-groups)
    const int jg = tid >> 6;
    const int rg = (tid >> 4) & 3;
    const int cg = tid & 15;
    // finalize mapping: fc = local col (0..63), frq*4.. = 4 rows
    const int fc  = tid >> 2;
    const int frq = tid & 3;

    const uint32_t ht0_u32 = smem_u32(ht0);
    const uint32_t ht1_u32 = smem_u32(ht1);
    // push offset (bytes) inside target buffer: [j = cbase+fc][row = frq*4]
    const uint32_t push_off = (uint32_t)(((cbase + fc) << 4) + (frq << 2)) * 4u;

    for (int t = 0; t < SEQ; t++) {
        const float* cur = (t & 1) ? ht1 : ht0;
        const uint32_t nxt_u32 = (t & 1) ? ht0_u32 : ht1_u32;

        if (tid < ROWS_PER_CL)
            toks[tid] = __ldg(&x[(rowBase + tid) * SEQ + t]);
        __syncthreads();   // toks ready; also fences scr reuse from prev step

        // prefetch E2 values (consumed after GEMM; latency hidden)
        float e2v[4];
#pragma unroll
        for (int rr = 0; rr < 4; rr++)
            e2v[rr] = __ldg(&d_E2[toks[frq * 4 + rr] * HID + cbase + fc]);

        // ---- GEMM1 partials: rows 16 x cols 64, this thread: 4x4 tile over
        //      its jg K-range, FFMA2 with row-pair accumulators ----
        ull a01[4], a23[4];
#pragma unroll
        for (int c = 0; c < 4; c++) { a01[c] = 0ull; a23[c] = 0ull; }
        {
            const ulonglong2* hp = ((const ulonglong2*)cur) + rg;   // idx j*4
            const float4*     wp = ((const float4*)whh) + cg;       // idx j*16
            const int j0 = jg << 7;
#pragma unroll 4
            for (int j = j0; j < j0 + 128; j++) {
                ulonglong2 hv = hp[j * 4];   // rows (rg*4+0,1) , (rg*4+2,3)
                float4     w  = wp[j * 16];  // cols cg*4 .. +3
                ull w0 = dup2(w.x), w1 = dup2(w.y), w2 = dup2(w.z), w3 = dup2(w.w);
                FFMA2(a01[0], hv.x, w0); FFMA2(a23[0], hv.y, w0);
                FFMA2(a01[1], hv.x, w1); FFMA2(a23[1], hv.y, w1);
                FFMA2(a01[2], hv.x, w2); FFMA2(a23[2], hv.y, w2);
                FFMA2(a01[3], hv.x, w3); FFMA2(a23[3], hv.y, w3);
            }
        }
        // transpose 4x4 tile to per-row float4, store to scr[jg][row][col]
        {
            float2 l0 = unpk(a01[0]), l1 = unpk(a01[1]), l2 = unpk(a01[2]), l3 = unpk(a01[3]);
            float2 h0 = unpk(a23[0]), h1 = unpk(a23[1]), h2 = unpk(a23[2]), h3 = unpk(a23[3]);
            float* sp = scr + jg * SCR_JG + (rg * 4) * SCR_STRIDE + cg * 4;
            *(float4*)(sp)                  = make_float4(l0.x, l1.x, l2.x, l3.x);
            *(float4*)(sp + SCR_STRIDE)     = make_float4(l0.y, l1.y, l2.y, l3.y);
            *(float4*)(sp + 2 * SCR_STRIDE) = make_float4(h0.x, h1.x, h2.x, h3.x);
            *(float4*)(sp + 3 * SCR_STRIDE) = make_float4(h0.y, h1.y, h2.y, h3.y);
        }
        __syncthreads();

        // ---- finalize: reduce 4 jg partials + E2, tanh ----
        float hn[4];
#pragma unroll
        for (int rr = 0; rr < 4; rr++) {
            int row = frq * 4 + rr;
            float s = scr[0 * SCR_JG + row * SCR_STRIDE + fc]
                    + scr[1 * SCR_JG + row * SCR_STRIDE + fc]
                    + scr[2 * SCR_JG + row * SCR_STRIDE + fc]
                    + scr[3 * SCR_JG + row * SCR_STRIDE + fc];
            hn[rr] = tanhf(e2v[rr] + s);
        }

        // ---- all-gather h_new slice into every cluster CTA's next buffer ----
        {
            const uint32_t a = nxt_u32 + push_off;
#pragma unroll
            for (int p = 0; p < CLUSTER_SZ; p++)
                st_cluster_v4(a, p, hn[0], hn[1], hn[2], hn[3]);
        }

        // ---- store h to global H (consumed by ygemm later) ----
#pragma unroll
        for (int rr = 0; rr < 4; rr++)
            d_H[(size_t)((rowBase + frq * 4 + rr) * SEQ + t) * HID + cbase + fc] = hn[rr];

        cluster_sync_();   // release pushes; next step may read nxt buffer
    }

    // ---- final hidden state output (h_T lives in ht0 since SEQ is even) ----
    if (write_h) {
        float* hout = out + (size_t)BATCH * SEQ * VOCAB;
#pragma unroll
        for (int rr = 0; rr < 4; rr++)
            hout[(rowBase + frq * 4 + rr) * HID + cbase + fc] =
                ht0[((cbase + fc) << 4) + frq * 4 + rr];
    }
}

// ---------------------------------------------------------------------------
// y = H @ W_ho + b_o   ([131072 x 512] @ [512 x 128]), fully parallel.
// out row index m = b*SEQ + t maps directly to out[b][t][:].
// ---------------------------------------------------------------------------
#define YMT 128
#define YKT 16
#define HT_STRIDE 132

__global__ void __launch_bounds__(256, 1)
ygemm_kernel(const float* __restrict__ Who,
             const float* __restrict__ bo,
             float* __restrict__ out) {
    __shared__ float Ht[YKT * HT_STRIDE];   // [k][row] transposed tile
    __shared__ float Wt[YKT * VOCAB];       // [k][vocab]

    const int tid = threadIdx.x;
    const int m0  = blockIdx.x * YMT;
    const int r0  = (tid >> 4) * 8;
    const int c0  = (tid & 15) * 8;

    ull acc[32];
#pragma unroll
    for (int i = 0; i < 32; i++) acc[i] = 0ull;

    for (int kt = 0; kt < HID / YKT; kt++) {
        // load + transpose H tile: [128 rows][16 k] -> Ht[k][row]
#pragma unroll
        for (int l = 0; l < 2; l++) {
            int i = tid + l * 256;
            int row = i >> 2, q = i & 3;
            float4 v = *(const float4*)&d_H[(size_t)(m0 + row) * HID + kt * YKT + q * 4];
            Ht[(q * 4 + 0) * HT_STRIDE + row] = v.x;
            Ht[(q * 4 + 1) * HT_STRIDE + row] = v.y;
            Ht[(q * 4 + 2) * HT_STRIDE + row] = v.z;
            Ht[(q * 4 + 3) * HT_STRIDE + row] = v.w;
        }
        // load W tile
#pragma unroll
        for (int l = 0; l < 2; l++) {
            int i = tid + l * 256;
            int k = i >> 5, c4 = i & 31;
            *(float4*)&Wt[k * VOCAB + c4 * 4] =
                *(const float4*)&Who[(kt * YKT + k) * VOCAB + c4 * 4];
        }
        __syncthreads();

#pragma unroll
        for (int k = 0; k < YKT; k++) {
            ulonglong2 hA = *(const ulonglong2*)&Ht[k * HT_STRIDE + r0];     // rows r0..+3
            ulonglong2 hB = *(const ulonglong2*)&Ht[k * HT_STRIDE + r0 + 4]; // rows r0+4..+7
            float4 wA = *(const float4*)&Wt[k * VOCAB + c0];
            float4 wB = *(const float4*)&Wt[k * VOCAB + c0 + 4];
            float wv[8] = {wA.x, wA.y, wA.z, wA.w, wB.x, wB.y, wB.z, wB.w};
#pragma unroll
            for (int c = 0; c < 8; c++) {
                ull wd = dup2(wv[c]);
                FFMA2(acc[c * 4 + 0], hA.x, wd);
                FFMA2(acc[c * 4 + 1], hA.y, wd);
                FFMA2(acc[c * 4 + 2], hB.x, wd);
                FFMA2(acc[c * 4 + 3], hB.y, wd);
            }
        }
        __syncthreads();
    }

    // epilogue
    float bo8[8];
#pragma unroll
    for (int c = 0; c < 8; c++) bo8[c] = __ldg(&bo[c0 + c]);

#pragma unroll
    for (int rr = 0; rr < 8; rr++) {
        int p = rr >> 1, half = rr & 1;
        float v[8];
#pragma unroll
        for (int c = 0; c < 8; c++) {
            float2 f = unpk(acc[c * 4 + p]);
            v[c] = (half ? f.y : f.x) + bo8[c];
        }
        float* op = &out[(size_t)(m0 + r0 + rr) * VOCAB + c0];
        *(float4*)(op)     = make_float4(v[0], v[1], v[2], v[3]);
        *(float4*)(op + 4) = make_float4(v[4], v[5], v[6], v[7]);
    }
}

// ---------------------------------------------------------------------------
extern "C" void kernel_launch(void* const* d_in, const int* in_sizes, int n_in,
                              void* d_out, int out_size) {
    const int*   x   = (const int*)  d_in[0];
    const float* emb = (const float*)d_in[1];
    const float* Wih = (const float*)d_in[2];
    const float* bih = (const float*)d_in[3];
    const float* Whh = (const float*)d_in[4];
    const float* bhh = (const float*)d_in[5];
    const float* Who = (const float*)d_in[6];
    const float* bo  = (const float*)d_in[7];
    float* out = (float*)d_out;

    int write_h = (out_size >= BATCH * SEQ * VOCAB + BATCH * HID) ? 1 : 0;

    cudaFuncSetAttribute(rnn_kernel,
                         cudaFuncAttributeMaxDynamicSharedMemorySize, SMEM_BYTES);

    e2_kernel<<<VOCAB, HID>>>(emb, Wih, bih, bhh);
    rnn_kernel<<<NUM_CLUSTERS * CLUSTER_SZ, NTHREADS, SMEM_BYTES>>>(x, Whh, out, write_h);
    ygemm_kernel<<<(BATCH * SEQ) / YMT, 256>>>(Who, bo, out);
}